// round 1
// baseline (speedup 1.0000x reference)
#include <cuda_runtime.h>
#include <math.h>

#define NN   50000
#define EE   600000
#define HIDN 128
#define HH   4
#define DDIM 32
#define RR   4
#define LLAY 2
#define MMOUT 10000

// ---------------- scratch (device globals; no allocations allowed) ----------------
__device__ float    g_h[NN * HIDN];
__device__ float    g_q[NN * HIDN];
__device__ float    g_k[NN * HIDN];
__device__ float    g_v[NN * HIDN];
__device__ float    g_kall[NN * RR * HIDN];   // [n][r][h][e]
__device__ float    g_vall[NN * RR * HIDN];
__device__ float    g_score[EE * HH];
__device__ unsigned g_segmax[NN * RR * HH];
__device__ float    g_segsum[NN * RR * HH];
__device__ float    g_attn[NN * HIDN];
__device__ float    g_stats[2 * HIDN];

// ---------------- helpers ----------------
__device__ __forceinline__ float gelu_f(float x) {
    return 0.5f * x * (1.0f + erff(x * 0.7071067811865475f));
}
__device__ __forceinline__ unsigned fmap(float f) {
    unsigned u = __float_as_uint(f);
    return (u & 0x80000000u) ? ~u : (u | 0x80000000u);
}
__device__ __forceinline__ float funmap(unsigned m) {
    return (m & 0x80000000u) ? __uint_as_float(m & 0x7FFFFFFFu) : __uint_as_float(~m);
}

// ---------------- fill ----------------
__global__ void fill_zero_kernel(unsigned* __restrict__ p, int n) {
    int i = blockIdx.x * blockDim.x + threadIdx.x;
    if (i < n) p[i] = 0u;
}

// ---------------- GEMM: C[M x 128] = act(A)[M x 128] @ B[128 x 128] + bias ----------------
// MODE 0: C = A@B + bias
// MODE 1: C = mix*(gelu(A)@B + bias) + (1-mix)*resid, mix = sigmoid(*skipv)
template <int MODE>
__global__ __launch_bounds__(128)
void gemm128_kernel(const float* __restrict__ A, const float* __restrict__ B,
                    const float* __restrict__ bias, float* __restrict__ C,
                    int Mrows, const float* __restrict__ resid,
                    const float* __restrict__ skipv) {
    __shared__ __align__(16) float Ast[32][68];   // transposed A chunk [k][row]
    __shared__ __align__(16) float Bs[32][128];

    int tid = threadIdx.x;
    int r0 = blockIdx.x * 64;
    int tr = tid >> 4;   // 0..7
    int tc = tid & 15;   // 0..15

    float acc[8][8];
#pragma unroll
    for (int i = 0; i < 8; i++)
#pragma unroll
        for (int j = 0; j < 8; j++) acc[i][j] = 0.0f;

    for (int kk = 0; kk < 128; kk += 32) {
        // load A chunk (transposed, optional gelu)
        {
            int kq = tid & 7;     // float4 idx within 32-wide k chunk
            int rr = tid >> 3;    // 0..15
#pragma unroll
            for (int p = 0; p < 4; p++) {
                int row = rr + p * 16;
                int grow = r0 + row;
                float4 va = make_float4(0.f, 0.f, 0.f, 0.f);
                if (grow < Mrows)
                    va = *reinterpret_cast<const float4*>(A + (size_t)grow * 128 + kk + kq * 4);
                if (MODE == 1) {
                    va.x = gelu_f(va.x); va.y = gelu_f(va.y);
                    va.z = gelu_f(va.z); va.w = gelu_f(va.w);
                }
                Ast[kq * 4 + 0][row] = va.x;
                Ast[kq * 4 + 1][row] = va.y;
                Ast[kq * 4 + 2][row] = va.z;
                Ast[kq * 4 + 3][row] = va.w;
            }
        }
        // load B chunk
        {
            int c4 = tid & 31;
            int kr = tid >> 5;   // 0..3
#pragma unroll
            for (int p = 0; p < 8; p++) {
                int k = kr + p * 4;
                *reinterpret_cast<float4*>(&Bs[k][c4 * 4]) =
                    *reinterpret_cast<const float4*>(B + (size_t)(kk + k) * 128 + c4 * 4);
            }
        }
        __syncthreads();
#pragma unroll 4
        for (int k = 0; k < 32; k++) {
            float a[8], b[8];
            float4 t;
            t = *reinterpret_cast<const float4*>(&Ast[k][tr * 8]);     a[0]=t.x; a[1]=t.y; a[2]=t.z; a[3]=t.w;
            t = *reinterpret_cast<const float4*>(&Ast[k][tr * 8 + 4]); a[4]=t.x; a[5]=t.y; a[6]=t.z; a[7]=t.w;
            t = *reinterpret_cast<const float4*>(&Bs[k][tc * 8]);      b[0]=t.x; b[1]=t.y; b[2]=t.z; b[3]=t.w;
            t = *reinterpret_cast<const float4*>(&Bs[k][tc * 8 + 4]);  b[4]=t.x; b[5]=t.y; b[6]=t.z; b[7]=t.w;
#pragma unroll
            for (int i = 0; i < 8; i++)
#pragma unroll
                for (int j = 0; j < 8; j++)
                    acc[i][j] = fmaf(a[i], b[j], acc[i][j]);
        }
        __syncthreads();
    }

    float mix = 1.0f, omix = 0.0f;
    if (MODE == 1) {
        float s = *skipv;
        mix = 1.0f / (1.0f + expf(-s));
        omix = 1.0f - mix;
    }
    float bv[8];
#pragma unroll
    for (int j = 0; j < 8; j++) bv[j] = bias[tc * 8 + j];

#pragma unroll
    for (int i = 0; i < 8; i++) {
        int grow = r0 + tr * 8 + i;
        if (grow >= Mrows) continue;
#pragma unroll
        for (int j = 0; j < 8; j += 4) {
            int col = tc * 8 + j;
            float4 r4;
            r4.x = acc[i][j + 0] + bv[j + 0];
            r4.y = acc[i][j + 1] + bv[j + 1];
            r4.z = acc[i][j + 2] + bv[j + 2];
            r4.w = acc[i][j + 3] + bv[j + 3];
            if (MODE == 1) {
                float4 old = *reinterpret_cast<const float4*>(resid + (size_t)grow * 128 + col);
                r4.x = mix * r4.x + omix * old.x;
                r4.y = mix * r4.y + omix * old.y;
                r4.z = mix * r4.z + omix * old.z;
                r4.w = mix * r4.w + omix * old.w;
            }
            *reinterpret_cast<float4*>(C + (size_t)grow * 128 + col) = r4;
        }
    }
}

// ---------------- BatchNorm stats + apply ----------------
__global__ void bn_stats_kernel(const float* __restrict__ h, float* __restrict__ stats, int n) {
    __shared__ float s_sum[256], s_sq[256];
    int tid = threadIdx.x;
    int c = tid & 127, half = tid >> 7;
    float sum = 0.f, sq = 0.f;
    for (int r = blockIdx.x * 2 + half; r < n; r += gridDim.x * 2) {
        float v = h[(size_t)r * 128 + c];
        sum += v; sq += v * v;
    }
    s_sum[tid] = sum; s_sq[tid] = sq;
    __syncthreads();
    if (half == 0) {
        atomicAdd(&stats[c], sum + s_sum[tid + 128]);
        atomicAdd(&stats[128 + c], sq + s_sq[tid + 128]);
    }
}

__global__ void bn_apply_kernel(float* __restrict__ h, const float* __restrict__ stats,
                                const float* __restrict__ gamma, const float* __restrict__ beta,
                                int n) {
    int i = blockIdx.x * blockDim.x + threadIdx.x;
    if (i >= n * 128) return;
    int c = i & 127;
    float mean = stats[c] * (1.0f / (float)NN);
    float var = stats[128 + c] * (1.0f / (float)NN) - mean * mean;
    h[i] = (h[i] - mean) * rsqrtf(var + 1e-5f) * gamma[c] + beta[c];
}

// ---------------- relation transforms: k_all[n,r,h,e] = sum_d k[n,h,d]*a_rel[r,h,d,e] ----------------
__global__ __launch_bounds__(512)
void rel_transform_kernel(const float* __restrict__ kin, const float* __restrict__ vin,
                          const float* __restrict__ a_rel, const float* __restrict__ m_rel,
                          int n) {
    __shared__ __align__(16) float ksh[2][128];
    __shared__ __align__(16) float vsh[2][128];
    int tid = threadIdx.x;
    int o = tid;                 // output slot: r*128 + h*32 + e
    int r = o >> 7, h = (o >> 5) & 3, e = o & 31;

    float wa[32], wm[32];
    const float* abase = a_rel + (size_t)((r * 4 + h) * 32) * 32 + e;
    const float* mbase = m_rel + (size_t)((r * 4 + h) * 32) * 32 + e;
#pragma unroll
    for (int d = 0; d < 32; d++) { wa[d] = abase[d * 32]; wm[d] = mbase[d * 32]; }

    for (int n0 = blockIdx.x * 2; n0 < n; n0 += gridDim.x * 2) {
        __syncthreads();
        {
            int which = tid >> 8;    // 0/1
            int cc = tid & 255;
            int node = n0 + which;
            if (node < n) {
                if (cc < 128) ksh[which][cc] = kin[(size_t)node * 128 + cc];
                else          vsh[which][cc - 128] = vin[(size_t)node * 128 + (cc - 128)];
            }
        }
        __syncthreads();
#pragma unroll
        for (int which = 0; which < 2; which++) {
            int node = n0 + which;
            if (node >= n) break;
            float accK = 0.f, accV = 0.f;
            const float* kr = &ksh[which][h * 32];
            const float* vr = &vsh[which][h * 32];
#pragma unroll
            for (int d4 = 0; d4 < 32; d4 += 4) {
                float4 kv = *reinterpret_cast<const float4*>(kr + d4);
                float4 vv = *reinterpret_cast<const float4*>(vr + d4);
                accK += kv.x * wa[d4] + kv.y * wa[d4 + 1] + kv.z * wa[d4 + 2] + kv.w * wa[d4 + 3];
                accV += vv.x * wm[d4] + vv.y * wm[d4 + 1] + vv.z * wm[d4 + 2] + vv.w * wm[d4 + 3];
            }
            g_kall[(size_t)node * 512 + o] = accK;
            g_vall[(size_t)node * 512 + o] = accV;
        }
    }
}

// ---------------- edge score + segment max ----------------
__global__ void score_kernel(const int* __restrict__ ei, const int* __restrict__ et,
                             const float* __restrict__ q, const float* __restrict__ p_rel,
                             float* __restrict__ score, unsigned* __restrict__ segmax) {
    int gid = blockIdx.x * blockDim.x + threadIdx.x;
    if (gid >= EE * HH) return;
    int e = gid >> 2, h = gid & 3;
    int src = ei[e], dst = ei[EE + e], r = et[e];
    const float4* qp = reinterpret_cast<const float4*>(q + (size_t)dst * 128 + h * 32);
    const float4* kp = reinterpret_cast<const float4*>(g_kall + (size_t)src * 512 + r * 128 + h * 32);
    float s = 0.f;
#pragma unroll
    for (int i = 0; i < 8; i++) {
        float4 a = qp[i], b = kp[i];
        s += a.x * b.x + a.y * b.y + a.z * b.z + a.w * b.w;
    }
    s *= p_rel[r * 4 + h] * 0.17677669529663687f;   // 1/sqrt(32)
    score[gid] = s;
    atomicMax(&segmax[(dst * 4 + r) * 4 + h], fmap(s));
}

// ---------------- exp + segment sum ----------------
__global__ void expsum_kernel(const int* __restrict__ ei, const int* __restrict__ et,
                              float* __restrict__ score, const unsigned* __restrict__ segmax,
                              float* __restrict__ segsum) {
    int gid = blockIdx.x * blockDim.x + threadIdx.x;
    if (gid >= EE * HH) return;
    int e = gid >> 2, h = gid & 3;
    int dst = ei[EE + e], r = et[e];
    int seg = (dst * 4 + r) * 4 + h;
    float m = funmap(segmax[seg]);
    float s = expf(score[gid] - m);
    score[gid] = s;
    atomicAdd(&segsum[seg], s);
}

// ---------------- aggregation: attn[dst] += alpha * v_all[src, r] ----------------
__global__ void agg_kernel(const int* __restrict__ ei, const int* __restrict__ et,
                           const float* __restrict__ score, const float* __restrict__ segsum,
                           float* __restrict__ attn) {
    int gid = blockIdx.x * blockDim.x + threadIdx.x;
    if (gid >= EE * HH) return;
    int e = gid >> 2, h = gid & 3;
    int src = ei[e], dst = ei[EE + e], r = et[e];
    float alpha = score[gid] / segsum[(dst * 4 + r) * 4 + h];
    const float4* vp = reinterpret_cast<const float4*>(g_vall + (size_t)src * 512 + r * 128 + h * 32);
    float* op = attn + (size_t)dst * 128 + h * 32;
#pragma unroll
    for (int i = 0; i < 8; i++) {
        float4 v = vp[i];
        asm volatile("red.global.add.v4.f32 [%0], {%1,%2,%3,%4};"
                     :: "l"(op + i * 4),
                        "f"(alpha * v.x), "f"(alpha * v.y),
                        "f"(alpha * v.z), "f"(alpha * v.w)
                     : "memory");
    }
}

// ---------------- gather ----------------
__global__ void gather_kernel(const int* __restrict__ idx, const float* __restrict__ h,
                              float* __restrict__ out) {
    int gid = blockIdx.x * blockDim.x + threadIdx.x;
    if (gid >= MMOUT * 32) return;
    int m = gid >> 5, c4 = gid & 31;
    reinterpret_cast<float4*>(out)[(size_t)m * 32 + c4] =
        reinterpret_cast<const float4*>(h + (size_t)idx[m] * 128)[c4];
}

// ---------------- launch ----------------
extern "C" void kernel_launch(void* const* d_in, const int* in_sizes, int n_in,
                              void* d_out, int out_size) {
    const float* x        = (const float*)d_in[0];
    const float* proj_w   = (const float*)d_in[1];
    const float* proj_b   = (const float*)d_in[2];
    const float* bn_gamma = (const float*)d_in[3];
    const float* bn_beta  = (const float*)d_in[4];
    const float* q_w      = (const float*)d_in[5];
    const float* q_b      = (const float*)d_in[6];
    const float* k_w      = (const float*)d_in[7];
    const float* k_b      = (const float*)d_in[8];
    const float* v_w      = (const float*)d_in[9];
    const float* v_b      = (const float*)d_in[10];
    const float* a_w      = (const float*)d_in[11];
    const float* a_b      = (const float*)d_in[12];
    const float* skip     = (const float*)d_in[13];
    const float* a_rel    = (const float*)d_in[14];
    const float* m_rel    = (const float*)d_in[15];
    const float* p_rel    = (const float*)d_in[16];
    const int*   edge_idx = (const int*)d_in[17];
    const int*   edge_typ = (const int*)d_in[18];
    const int*   idx      = (const int*)d_in[19];
    float*       out      = (float*)d_out;

    float *p_h, *p_q, *p_k, *p_v, *p_score, *p_segsum, *p_attn, *p_stats;
    unsigned* p_segmax;
    cudaGetSymbolAddress((void**)&p_h, g_h);
    cudaGetSymbolAddress((void**)&p_q, g_q);
    cudaGetSymbolAddress((void**)&p_k, g_k);
    cudaGetSymbolAddress((void**)&p_v, g_v);
    cudaGetSymbolAddress((void**)&p_score, g_score);
    cudaGetSymbolAddress((void**)&p_segmax, g_segmax);
    cudaGetSymbolAddress((void**)&p_segsum, g_segsum);
    cudaGetSymbolAddress((void**)&p_attn, g_attn);
    cudaGetSymbolAddress((void**)&p_stats, g_stats);

    const int gemmGrid = (NN + 63) / 64;
    const int ehThreads = EE * HH;
    const int ehBlocks = (ehThreads + 255) / 256;

    // proj + BN
    fill_zero_kernel<<<1, 256>>>((unsigned*)p_stats, 2 * HIDN);
    gemm128_kernel<0><<<gemmGrid, 128>>>(x, proj_w, proj_b, p_h, NN, nullptr, nullptr);
    bn_stats_kernel<<<512, 256>>>(p_h, p_stats, NN);
    bn_apply_kernel<<<(NN * 128 + 255) / 256, 256>>>(p_h, p_stats, bn_gamma, bn_beta, NN);

    for (int l = 0; l < LLAY; l++) {
        const float* qwl = q_w + (size_t)l * 128 * 128;
        const float* kwl = k_w + (size_t)l * 128 * 128;
        const float* vwl = v_w + (size_t)l * 128 * 128;
        const float* awl = a_w + (size_t)l * 128 * 128;
        const float* qbl = q_b + (size_t)l * 128;
        const float* kbl = k_b + (size_t)l * 128;
        const float* vbl = v_b + (size_t)l * 128;
        const float* abl = a_b + (size_t)l * 128;
        const float* arl = a_rel + (size_t)l * RR * HH * DDIM * DDIM;
        const float* mrl = m_rel + (size_t)l * RR * HH * DDIM * DDIM;
        const float* prl = p_rel + (size_t)l * RR * HH;
        const float* skl = skip + l;

        gemm128_kernel<0><<<gemmGrid, 128>>>(p_h, qwl, qbl, p_q, NN, nullptr, nullptr);
        gemm128_kernel<0><<<gemmGrid, 128>>>(p_h, kwl, kbl, p_k, NN, nullptr, nullptr);
        gemm128_kernel<0><<<gemmGrid, 128>>>(p_h, vwl, vbl, p_v, NN, nullptr, nullptr);

        rel_transform_kernel<<<4096, 512>>>(p_k, p_v, arl, mrl, NN);

        fill_zero_kernel<<<(NN * RR * HH + 255) / 256, 256>>>(p_segmax, NN * RR * HH);
        fill_zero_kernel<<<(NN * RR * HH + 255) / 256, 256>>>((unsigned*)p_segsum, NN * RR * HH);

        score_kernel<<<ehBlocks, 256>>>(edge_idx, edge_typ, p_q, prl, p_score, p_segmax);
        expsum_kernel<<<ehBlocks, 256>>>(edge_idx, edge_typ, p_score, p_segmax, p_segsum);

        fill_zero_kernel<<<(NN * 128 + 255) / 256, 256>>>((unsigned*)p_attn, NN * 128);
        agg_kernel<<<ehBlocks, 256>>>(edge_idx, edge_typ, p_score, p_segsum, p_attn);

        gemm128_kernel<1><<<gemmGrid, 128>>>(p_attn, awl, abl, p_h, NN, p_h, skl);
    }

    gather_kernel<<<(MMOUT * 32 + 255) / 256, 256>>>(idx, p_h, out);
}

// round 2
// speedup vs baseline: 1.0298x; 1.0298x over previous
#include <cuda_runtime.h>
#include <math.h>

#define NN   50000
#define EE   600000
#define HIDN 128
#define HH   4
#define DDIM 32
#define RR   4
#define LLAY 2
#define MMOUT 10000

typedef unsigned long long u64;

// ---------------- scratch (device globals; no allocations allowed) ----------------
__device__ float    g_h[NN * HIDN];
__device__ float    g_q[NN * HIDN];
__device__ float    g_k[NN * HIDN];
__device__ float    g_v[NN * HIDN];
__device__ float    g_kall[NN * RR * HIDN];   // [n][r][h][e]
__device__ float    g_vall[NN * RR * HIDN];
__device__ float    g_score[EE * HH];
__device__ unsigned g_segmax[NN * RR * HH];
__device__ float    g_segsum[NN * RR * HH];
__device__ float    g_attn[NN * HIDN];
__device__ float    g_stats[2 * HIDN];

// ---------------- f32x2 helpers ----------------
__device__ __forceinline__ void fma2(u64& d, u64 a, u64 b) {
    asm("fma.rn.f32x2 %0, %1, %2, %0;" : "+l"(d) : "l"(a), "l"(b));
}
__device__ __forceinline__ u64 packdup(float s) {
    u64 r; asm("mov.b64 %0, {%1, %1};" : "=l"(r) : "f"(s)); return r;
}
__device__ __forceinline__ u64 pack2(float lo, float hi) {
    u64 r; asm("mov.b64 %0, {%1, %2};" : "=l"(r) : "f"(lo), "f"(hi)); return r;
}
__device__ __forceinline__ void unpack2(u64 v, float& lo, float& hi) {
    asm("mov.b64 {%0, %1}, %2;" : "=f"(lo), "=f"(hi) : "l"(v));
}

// ---------------- helpers ----------------
__device__ __forceinline__ float gelu_f(float x) {
    return 0.5f * x * (1.0f + erff(x * 0.7071067811865475f));
}
__device__ __forceinline__ unsigned fmap(float f) {
    unsigned u = __float_as_uint(f);
    return (u & 0x80000000u) ? ~u : (u | 0x80000000u);
}
__device__ __forceinline__ float funmap(unsigned m) {
    return (m & 0x80000000u) ? __uint_as_float(m & 0x7FFFFFFFu) : __uint_as_float(~m);
}

// ---------------- fill ----------------
__global__ void fill_zero_kernel(unsigned* __restrict__ p, int n) {
    int i = blockIdx.x * blockDim.x + threadIdx.x;
    if (i < n) p[i] = 0u;
}

// ---------------- GEMM: C[M x 128] = act(A)[M x 128] @ B[128 x 128] + bias ----------------
// MODE 0: C = A@B + bias
// MODE 1: C = mix*(gelu(A)@B + bias) + (1-mix)*resid, mix = sigmoid(*skipv)
template <int MODE>
__global__ __launch_bounds__(128)
void gemm128_kernel(const float* __restrict__ A, const float* __restrict__ B,
                    const float* __restrict__ bias, float* __restrict__ C,
                    int Mrows, const float* __restrict__ resid,
                    const float* __restrict__ skipv) {
    __shared__ __align__(16) float Ast[32][68];   // transposed A chunk [k][row]
    __shared__ __align__(16) float Bs[32][128];

    int tid = threadIdx.x;
    int r0 = blockIdx.x * 64;
    int tr = tid >> 4;   // 0..7
    int tc = tid & 15;   // 0..15

    // packed accumulators: acc2[i][j2] = (C[i][2*j2], C[i][2*j2+1]) within 8x8 microtile
    u64 acc2[8][4];
#pragma unroll
    for (int i = 0; i < 8; i++)
#pragma unroll
        for (int j = 0; j < 4; j++) acc2[i][j] = 0ull;

    for (int kk = 0; kk < 128; kk += 32) {
        // load A chunk (transposed, optional gelu)
        {
            int kq = tid & 7;     // float4 idx within 32-wide k chunk
            int rr = tid >> 3;    // 0..15
#pragma unroll
            for (int p = 0; p < 4; p++) {
                int row = rr + p * 16;
                int grow = r0 + row;
                float4 va = make_float4(0.f, 0.f, 0.f, 0.f);
                if (grow < Mrows)
                    va = *reinterpret_cast<const float4*>(A + (size_t)grow * 128 + kk + kq * 4);
                if (MODE == 1) {
                    va.x = gelu_f(va.x); va.y = gelu_f(va.y);
                    va.z = gelu_f(va.z); va.w = gelu_f(va.w);
                }
                Ast[kq * 4 + 0][row] = va.x;
                Ast[kq * 4 + 1][row] = va.y;
                Ast[kq * 4 + 2][row] = va.z;
                Ast[kq * 4 + 3][row] = va.w;
            }
        }
        // load B chunk
        {
            int c4 = tid & 31;
            int kr = tid >> 5;   // 0..3
#pragma unroll
            for (int p = 0; p < 8; p++) {
                int k = kr + p * 4;
                *reinterpret_cast<float4*>(&Bs[k][c4 * 4]) =
                    *reinterpret_cast<const float4*>(B + (size_t)(kk + k) * 128 + c4 * 4);
            }
        }
        __syncthreads();
#pragma unroll 4
        for (int k = 0; k < 32; k++) {
            float4 t0 = *reinterpret_cast<const float4*>(&Ast[k][tr * 8]);
            float4 t1 = *reinterpret_cast<const float4*>(&Ast[k][tr * 8 + 4]);
            u64 a2[8];
            a2[0] = packdup(t0.x); a2[1] = packdup(t0.y);
            a2[2] = packdup(t0.z); a2[3] = packdup(t0.w);
            a2[4] = packdup(t1.x); a2[5] = packdup(t1.y);
            a2[6] = packdup(t1.z); a2[7] = packdup(t1.w);
            ulonglong2 tb0 = *reinterpret_cast<const ulonglong2*>(&Bs[k][tc * 8]);
            ulonglong2 tb1 = *reinterpret_cast<const ulonglong2*>(&Bs[k][tc * 8 + 4]);
            u64 b2[4] = {tb0.x, tb0.y, tb1.x, tb1.y};
#pragma unroll
            for (int i = 0; i < 8; i++)
#pragma unroll
                for (int j = 0; j < 4; j++)
                    fma2(acc2[i][j], a2[i], b2[j]);
        }
        __syncthreads();
    }

    float mix = 1.0f, omix = 0.0f;
    if (MODE == 1) {
        float s = *skipv;
        mix = 1.0f / (1.0f + expf(-s));
        omix = 1.0f - mix;
    }
    float bv[8];
#pragma unroll
    for (int j = 0; j < 8; j++) bv[j] = bias[tc * 8 + j];

#pragma unroll
    for (int i = 0; i < 8; i++) {
        int grow = r0 + tr * 8 + i;
        if (grow >= Mrows) continue;
        float accf[8];
#pragma unroll
        for (int j2 = 0; j2 < 4; j2++)
            unpack2(acc2[i][j2], accf[2 * j2], accf[2 * j2 + 1]);
#pragma unroll
        for (int j = 0; j < 8; j += 4) {
            int col = tc * 8 + j;
            float4 r4;
            r4.x = accf[j + 0] + bv[j + 0];
            r4.y = accf[j + 1] + bv[j + 1];
            r4.z = accf[j + 2] + bv[j + 2];
            r4.w = accf[j + 3] + bv[j + 3];
            if (MODE == 1) {
                float4 old = *reinterpret_cast<const float4*>(resid + (size_t)grow * 128 + col);
                r4.x = mix * r4.x + omix * old.x;
                r4.y = mix * r4.y + omix * old.y;
                r4.z = mix * r4.z + omix * old.z;
                r4.w = mix * r4.w + omix * old.w;
            }
            *reinterpret_cast<float4*>(C + (size_t)grow * 128 + col) = r4;
        }
    }
}

// ---------------- BatchNorm stats + apply ----------------
__global__ void bn_stats_kernel(const float* __restrict__ h, float* __restrict__ stats, int n) {
    __shared__ float s_sum[256], s_sq[256];
    int tid = threadIdx.x;
    int c = tid & 127, half = tid >> 7;
    float sum = 0.f, sq = 0.f;
    for (int r = blockIdx.x * 2 + half; r < n; r += gridDim.x * 2) {
        float v = h[(size_t)r * 128 + c];
        sum += v; sq += v * v;
    }
    s_sum[tid] = sum; s_sq[tid] = sq;
    __syncthreads();
    if (half == 0) {
        atomicAdd(&stats[c], sum + s_sum[tid + 128]);
        atomicAdd(&stats[128 + c], sq + s_sq[tid + 128]);
    }
}

__global__ void bn_apply_kernel(float* __restrict__ h, const float* __restrict__ stats,
                                const float* __restrict__ gamma, const float* __restrict__ beta,
                                int n) {
    int i = blockIdx.x * blockDim.x + threadIdx.x;
    if (i >= n * 128) return;
    int c = i & 127;
    float mean = stats[c] * (1.0f / (float)NN);
    float var = stats[128 + c] * (1.0f / (float)NN) - mean * mean;
    h[i] = (h[i] - mean) * rsqrtf(var + 1e-5f) * gamma[c] + beta[c];
}

// ---------------- relation transforms: k_all[n,r,h,e] = sum_d k[n,h,d]*a_rel[r,h,d,e] ----------------
// f32x2: (k,v) processed as packed pairs against (a_rel, m_rel) weight pairs.
__global__ __launch_bounds__(512)
void rel_transform_kernel(const float* __restrict__ kin, const float* __restrict__ vin,
                          const float* __restrict__ a_rel, const float* __restrict__ m_rel,
                          int n) {
    __shared__ __align__(16) float kvsh[2][256];   // interleaved (k[c], v[c]) pairs
    int tid = threadIdx.x;
    int o = tid;                 // output slot: r*128 + h*32 + e
    int r = o >> 7, h = (o >> 5) & 3, e = o & 31;

    // packed weights: w2[d] = (a_rel[r,h,d,e], m_rel[r,h,d,e])
    u64 w2[32];
    {
        const float* abase = a_rel + (size_t)((r * 4 + h) * 32) * 32 + e;
        const float* mbase = m_rel + (size_t)((r * 4 + h) * 32) * 32 + e;
#pragma unroll
        for (int d = 0; d < 32; d++) w2[d] = pack2(abase[d * 32], mbase[d * 32]);
    }

    for (int n0 = blockIdx.x * 2; n0 < n; n0 += gridDim.x * 2) {
        __syncthreads();
        {
            int which = tid >> 8;    // 0/1
            int cc = tid & 255;
            int node = n0 + which;
            if (node < n) {
                if (cc < 128) kvsh[which][2 * cc] = kin[(size_t)node * 128 + cc];
                else          kvsh[which][2 * (cc - 128) + 1] = vin[(size_t)node * 128 + (cc - 128)];
            }
        }
        __syncthreads();
#pragma unroll
        for (int which = 0; which < 2; which++) {
            int node = n0 + which;
            if (node >= n) break;
            u64 acc = 0ull;
            const ulonglong2* kv = reinterpret_cast<const ulonglong2*>(&kvsh[which][h * 64]);
#pragma unroll
            for (int d2 = 0; d2 < 16; d2++) {
                ulonglong2 p = kv[d2];
                fma2(acc, p.x, w2[2 * d2]);
                fma2(acc, p.y, w2[2 * d2 + 1]);
            }
            float accK, accV;
            unpack2(acc, accK, accV);
            g_kall[(size_t)node * 512 + o] = accK;
            g_vall[(size_t)node * 512 + o] = accV;
        }
    }
}

// ---------------- edge score + segment max ----------------
__global__ void score_kernel(const int* __restrict__ ei, const int* __restrict__ et,
                             const float* __restrict__ q, const float* __restrict__ p_rel,
                             float* __restrict__ score, unsigned* __restrict__ segmax) {
    int gid = blockIdx.x * blockDim.x + threadIdx.x;
    if (gid >= EE * HH) return;
    int e = gid >> 2, h = gid & 3;
    int src = ei[e], dst = ei[EE + e], r = et[e];
    const ulonglong2* qp = reinterpret_cast<const ulonglong2*>(q + (size_t)dst * 128 + h * 32);
    const ulonglong2* kp = reinterpret_cast<const ulonglong2*>(g_kall + (size_t)src * 512 + r * 128 + h * 32);
    u64 acc = 0ull;
#pragma unroll
    for (int i = 0; i < 8; i++) {
        ulonglong2 a = qp[i], b = kp[i];
        fma2(acc, a.x, b.x);
        fma2(acc, a.y, b.y);
    }
    float s0, s1;
    unpack2(acc, s0, s1);
    float s = (s0 + s1) * p_rel[r * 4 + h] * 0.17677669529663687f;   // 1/sqrt(32)
    score[gid] = s;
    atomicMax(&segmax[(dst * 4 + r) * 4 + h], fmap(s));
}

// ---------------- exp + segment sum ----------------
__global__ void expsum_kernel(const int* __restrict__ ei, const int* __restrict__ et,
                              float* __restrict__ score, const unsigned* __restrict__ segmax,
                              float* __restrict__ segsum) {
    int gid = blockIdx.x * blockDim.x + threadIdx.x;
    if (gid >= EE * HH) return;
    int e = gid >> 2, h = gid & 3;
    int dst = ei[EE + e], r = et[e];
    int seg = (dst * 4 + r) * 4 + h;
    float m = funmap(segmax[seg]);
    float s = expf(score[gid] - m);
    score[gid] = s;
    atomicAdd(&segsum[seg], s);
}

// ---------------- aggregation: attn[dst] += alpha * v_all[src, r] ----------------
__global__ void agg_kernel(const int* __restrict__ ei, const int* __restrict__ et,
                           const float* __restrict__ score, const float* __restrict__ segsum,
                           float* __restrict__ attn) {
    int gid = blockIdx.x * blockDim.x + threadIdx.x;
    if (gid >= EE * HH) return;
    int e = gid >> 2, h = gid & 3;
    int src = ei[e], dst = ei[EE + e], r = et[e];
    float alpha = score[gid] / segsum[(dst * 4 + r) * 4 + h];
    const float4* vp = reinterpret_cast<const float4*>(g_vall + (size_t)src * 512 + r * 128 + h * 32);
    float* op = attn + (size_t)dst * 128 + h * 32;
#pragma unroll
    for (int i = 0; i < 8; i++) {
        float4 v = vp[i];
        asm volatile("red.global.add.v4.f32 [%0], {%1,%2,%3,%4};"
                     :: "l"(op + i * 4),
                        "f"(alpha * v.x), "f"(alpha * v.y),
                        "f"(alpha * v.z), "f"(alpha * v.w)
                     : "memory");
    }
}

// ---------------- gather ----------------
__global__ void gather_kernel(const int* __restrict__ idx, const float* __restrict__ h,
                              float* __restrict__ out) {
    int gid = blockIdx.x * blockDim.x + threadIdx.x;
    if (gid >= MMOUT * 32) return;
    int m = gid >> 5, c4 = gid & 31;
    reinterpret_cast<float4*>(out)[(size_t)m * 32 + c4] =
        reinterpret_cast<const float4*>(h + (size_t)idx[m] * 128)[c4];
}

// ---------------- launch ----------------
extern "C" void kernel_launch(void* const* d_in, const int* in_sizes, int n_in,
                              void* d_out, int out_size) {
    const float* x        = (const float*)d_in[0];
    const float* proj_w   = (const float*)d_in[1];
    const float* proj_b   = (const float*)d_in[2];
    const float* bn_gamma = (const float*)d_in[3];
    const float* bn_beta  = (const float*)d_in[4];
    const float* q_w      = (const float*)d_in[5];
    const float* q_b      = (const float*)d_in[6];
    const float* k_w      = (const float*)d_in[7];
    const float* k_b      = (const float*)d_in[8];
    const float* v_w      = (const float*)d_in[9];
    const float* v_b      = (const float*)d_in[10];
    const float* a_w      = (const float*)d_in[11];
    const float* a_b      = (const float*)d_in[12];
    const float* skip     = (const float*)d_in[13];
    const float* a_rel    = (const float*)d_in[14];
    const float* m_rel    = (const float*)d_in[15];
    const float* p_rel    = (const float*)d_in[16];
    const int*   edge_idx = (const int*)d_in[17];
    const int*   edge_typ = (const int*)d_in[18];
    const int*   idx      = (const int*)d_in[19];
    float*       out      = (float*)d_out;

    float *p_h, *p_q, *p_k, *p_v, *p_score, *p_segsum, *p_attn, *p_stats;
    unsigned* p_segmax;
    cudaGetSymbolAddress((void**)&p_h, g_h);
    cudaGetSymbolAddress((void**)&p_q, g_q);
    cudaGetSymbolAddress((void**)&p_k, g_k);
    cudaGetSymbolAddress((void**)&p_v, g_v);
    cudaGetSymbolAddress((void**)&p_score, g_score);
    cudaGetSymbolAddress((void**)&p_segmax, g_segmax);
    cudaGetSymbolAddress((void**)&p_segsum, g_segsum);
    cudaGetSymbolAddress((void**)&p_attn, g_attn);
    cudaGetSymbolAddress((void**)&p_stats, g_stats);

    const int gemmGrid = (NN + 63) / 64;
    const int ehThreads = EE * HH;
    const int ehBlocks = (ehThreads + 255) / 256;

    // proj + BN
    fill_zero_kernel<<<1, 256>>>((unsigned*)p_stats, 2 * HIDN);
    gemm128_kernel<0><<<gemmGrid, 128>>>(x, proj_w, proj_b, p_h, NN, nullptr, nullptr);
    bn_stats_kernel<<<512, 256>>>(p_h, p_stats, NN);
    bn_apply_kernel<<<(NN * 128 + 255) / 256, 256>>>(p_h, p_stats, bn_gamma, bn_beta, NN);

    for (int l = 0; l < LLAY; l++) {
        const float* qwl = q_w + (size_t)l * 128 * 128;
        const float* kwl = k_w + (size_t)l * 128 * 128;
        const float* vwl = v_w + (size_t)l * 128 * 128;
        const float* awl = a_w + (size_t)l * 128 * 128;
        const float* qbl = q_b + (size_t)l * 128;
        const float* kbl = k_b + (size_t)l * 128;
        const float* vbl = v_b + (size_t)l * 128;
        const float* abl = a_b + (size_t)l * 128;
        const float* arl = a_rel + (size_t)l * RR * HH * DDIM * DDIM;
        const float* mrl = m_rel + (size_t)l * RR * HH * DDIM * DDIM;
        const float* prl = p_rel + (size_t)l * RR * HH;
        const float* skl = skip + l;

        gemm128_kernel<0><<<gemmGrid, 128>>>(p_h, qwl, qbl, p_q, NN, nullptr, nullptr);
        gemm128_kernel<0><<<gemmGrid, 128>>>(p_h, kwl, kbl, p_k, NN, nullptr, nullptr);
        gemm128_kernel<0><<<gemmGrid, 128>>>(p_h, vwl, vbl, p_v, NN, nullptr, nullptr);

        rel_transform_kernel<<<4096, 512>>>(p_k, p_v, arl, mrl, NN);

        fill_zero_kernel<<<(NN * RR * HH + 255) / 256, 256>>>(p_segmax, NN * RR * HH);
        fill_zero_kernel<<<(NN * RR * HH + 255) / 256, 256>>>((unsigned*)p_segsum, NN * RR * HH);

        score_kernel<<<ehBlocks, 256>>>(edge_idx, edge_typ, p_q, prl, p_score, p_segmax);
        expsum_kernel<<<ehBlocks, 256>>>(edge_idx, edge_typ, p_score, p_segmax, p_segsum);

        fill_zero_kernel<<<(NN * 128 + 255) / 256, 256>>>((unsigned*)p_attn, NN * 128);
        agg_kernel<<<ehBlocks, 256>>>(edge_idx, edge_typ, p_score, p_segsum, p_attn);

        gemm128_kernel<1><<<gemmGrid, 128>>>(p_attn, awl, abl, p_h, NN, p_h, skl);
    }

    gather_kernel<<<(MMOUT * 32 + 255) / 256, 256>>>(idx, p_h, out);
}

// round 3
// speedup vs baseline: 1.3025x; 1.2648x over previous
#include <cuda_runtime.h>
#include <math.h>

#define NN   50000
#define EE   600000
#define HIDN 128
#define HH   4
#define DDIM 32
#define RR   4
#define LLAY 2
#define MMOUT 10000
#define NSEG (NN * RR)                 // 200000 softmax segments
#define SCAN_CHUNK 4096
#define SCAN_B ((NSEG + SCAN_CHUNK - 1) / SCAN_CHUNK)   // 49

typedef unsigned long long u64;

// ---------------- scratch (device globals; no allocations allowed) ----------------
__device__ float g_h[NN * HIDN];
__device__ float g_q[NN * HIDN];
__device__ float g_k[NN * HIDN];
__device__ float g_v[NN * HIDN];
__device__ float g_kall[NN * RR * HIDN];   // [n][r][h][e]
__device__ float g_vall[NN * RR * HIDN];
__device__ float g_attn[NN * HIDN];
__device__ float g_stats[2 * HIDN];
// CSR scratch
__device__ int   g_counts[NSEG];
__device__ int   g_offs[NSEG + 1];
__device__ int   g_cursor[NSEG];
__device__ int   g_bsum[SCAN_B];
__device__ int   g_boff[SCAN_B];
__device__ int   g_ssrc[EE];

// ---------------- f32x2 helpers ----------------
__device__ __forceinline__ void fma2(u64& d, u64 a, u64 b) {
    asm("fma.rn.f32x2 %0, %1, %2, %0;" : "+l"(d) : "l"(a), "l"(b));
}
__device__ __forceinline__ u64 packdup(float s) {
    u64 r; asm("mov.b64 %0, {%1, %1};" : "=l"(r) : "f"(s)); return r;
}
__device__ __forceinline__ u64 pack2(float lo, float hi) {
    u64 r; asm("mov.b64 %0, {%1, %2};" : "=l"(r) : "f"(lo), "f"(hi)); return r;
}
__device__ __forceinline__ void unpack2(u64 v, float& lo, float& hi) {
    asm("mov.b64 {%0, %1}, %2;" : "=f"(lo), "=f"(hi) : "l"(v));
}

__device__ __forceinline__ float gelu_f(float x) {
    return 0.5f * x * (1.0f + erff(x * 0.7071067811865475f));
}

// ---------------- fill ----------------
__global__ void fill_zero_kernel(unsigned* __restrict__ p, int n) {
    int i = blockIdx.x * blockDim.x + threadIdx.x;
    if (i < n) p[i] = 0u;
}

// ================= CSR build: counting sort of edges by seg = dst*4 + rel =================
__global__ void hist_kernel(const int* __restrict__ ei, const int* __restrict__ et,
                            int* __restrict__ counts) {
    int e = blockIdx.x * blockDim.x + threadIdx.x;
    if (e >= EE) return;
    int dst = ei[EE + e], r = et[e];
    atomicAdd(&counts[dst * 4 + r], 1);
}

__global__ __launch_bounds__(1024)
void scan_pass1(const int* __restrict__ counts, int* __restrict__ bsum) {
    __shared__ int swarp[32];
    int b = blockIdx.x, t = threadIdx.x;
    int base = b * SCAN_CHUNK + t * 4;
    int tot = 0;
#pragma unroll
    for (int j = 0; j < 4; j++) {
        int idx = base + j;
        tot += (idx < NSEG) ? counts[idx] : 0;
    }
#pragma unroll
    for (int d = 16; d; d >>= 1) tot += __shfl_xor_sync(0xffffffffu, tot, d);
    if ((t & 31) == 0) swarp[t >> 5] = tot;
    __syncthreads();
    if (t < 32) {
        int v = swarp[t];
#pragma unroll
        for (int d = 16; d; d >>= 1) v += __shfl_xor_sync(0xffffffffu, v, d);
        if (t == 0) bsum[b] = v;
    }
}

__global__ void scan_pass2(const int* __restrict__ bsum, int* __restrict__ boff,
                           int* __restrict__ offs) {
    if (threadIdx.x == 0 && blockIdx.x == 0) {
        int run = 0;
        for (int i = 0; i < SCAN_B; i++) { boff[i] = run; run += bsum[i]; }
        offs[NSEG] = run;
    }
}

__global__ __launch_bounds__(1024)
void scan_pass3(const int* __restrict__ counts, const int* __restrict__ boff,
                int* __restrict__ offs, int* __restrict__ cursor) {
    __shared__ int swarp[32];
    int b = blockIdx.x, t = threadIdx.x;
    int base = b * SCAN_CHUNK + t * 4;
    int c[4]; int tot = 0;
#pragma unroll
    for (int j = 0; j < 4; j++) {
        int idx = base + j;
        c[j] = (idx < NSEG) ? counts[idx] : 0;
        tot += c[j];
    }
    int lane = t & 31, w = t >> 5;
    int v = tot;
#pragma unroll
    for (int d = 1; d < 32; d <<= 1) {
        int n = __shfl_up_sync(0xffffffffu, v, d);
        if (lane >= d) v += n;
    }
    if (lane == 31) swarp[w] = v;
    __syncthreads();
    if (w == 0) {
        int sv = swarp[lane];
#pragma unroll
        for (int d = 1; d < 32; d <<= 1) {
            int n = __shfl_up_sync(0xffffffffu, sv, d);
            if (lane >= d) sv += n;
        }
        swarp[lane] = sv;
    }
    __syncthreads();
    int excl = v - tot + ((w > 0) ? swarp[w - 1] : 0) + boff[b];
#pragma unroll
    for (int j = 0; j < 4; j++) {
        int idx = base + j;
        if (idx < NSEG) { offs[idx] = excl; cursor[idx] = excl; }
        excl += c[j];
    }
}

__global__ void scatter_kernel(const int* __restrict__ ei, const int* __restrict__ et,
                               int* __restrict__ cursor, int* __restrict__ ssrc) {
    int e = blockIdx.x * blockDim.x + threadIdx.x;
    if (e >= EE) return;
    int src = ei[e], dst = ei[EE + e], r = et[e];
    int pos = atomicAdd(&cursor[dst * 4 + r], 1);
    ssrc[pos] = src;
}

// ================= fused edge attention: one warp per dst node =================
__global__ __launch_bounds__(256)
void edge_attn_kernel(const float* __restrict__ q, const int* __restrict__ offs,
                      const int* __restrict__ ssrc, const float* __restrict__ p_rel,
                      float* __restrict__ attn) {
    int wid = (blockIdx.x * (int)blockDim.x + (int)threadIdx.x) >> 5;
    int lane = threadIdx.x & 31;
    if (wid >= NN) return;
    const int node = wid;
    const float SCALE = 0.17677669529663687f;   // 1/sqrt(32)

    const float* qb = q + (size_t)node * 128;
    float q0 = qb[lane], q1 = qb[32 + lane], q2 = qb[64 + lane], q3 = qb[96 + lane];
    float o0 = 0.f, o1 = 0.f, o2 = 0.f, o3 = 0.f;

    int obase = node * 4;
#pragma unroll
    for (int r = 0; r < 4; r++) {
        int s = offs[obase + r], e = offs[obase + r + 1];
        if (s >= e) continue;
        float pr0 = p_rel[r * 4 + 0] * SCALE;
        float pr1 = p_rel[r * 4 + 1] * SCALE;
        float pr2 = p_rel[r * 4 + 2] * SCALE;
        float pr3 = p_rel[r * 4 + 3] * SCALE;
        float m0 = -INFINITY, m1 = -INFINITY, m2 = -INFINITY, m3 = -INFINITY;
        float z0 = 0.f, z1 = 0.f, z2 = 0.f, z3 = 0.f;
        float a0 = 0.f, a1 = 0.f, a2 = 0.f, a3 = 0.f;

        for (int pos = s; pos < e; pos++) {
            int src = __ldg(&ssrc[pos]);
            const float* kb = g_kall + (size_t)src * 512 + r * 128;
            const float* vb = g_vall + (size_t)src * 512 + r * 128;
            float k0 = kb[lane], k1 = kb[32 + lane], k2 = kb[64 + lane], k3 = kb[96 + lane];
            float v0 = vb[lane], v1 = vb[32 + lane], v2 = vb[64 + lane], v3 = vb[96 + lane];
            float s0 = q0 * k0, s1 = q1 * k1, s2 = q2 * k2, s3 = q3 * k3;
#pragma unroll
            for (int d = 16; d; d >>= 1) {
                s0 += __shfl_xor_sync(0xffffffffu, s0, d);
                s1 += __shfl_xor_sync(0xffffffffu, s1, d);
                s2 += __shfl_xor_sync(0xffffffffu, s2, d);
                s3 += __shfl_xor_sync(0xffffffffu, s3, d);
            }
            s0 *= pr0; s1 *= pr1; s2 *= pr2; s3 *= pr3;
            // online softmax per head (single exp per head; branches warp-uniform)
            if (s0 > m0) { float ex = __expf(m0 - s0); z0 = z0 * ex + 1.f; a0 = a0 * ex + v0; m0 = s0; }
            else         { float ex = __expf(s0 - m0); z0 += ex; a0 += ex * v0; }
            if (s1 > m1) { float ex = __expf(m1 - s1); z1 = z1 * ex + 1.f; a1 = a1 * ex + v1; m1 = s1; }
            else         { float ex = __expf(s1 - m1); z1 += ex; a1 += ex * v1; }
            if (s2 > m2) { float ex = __expf(m2 - s2); z2 = z2 * ex + 1.f; a2 = a2 * ex + v2; m2 = s2; }
            else         { float ex = __expf(s2 - m2); z2 += ex; a2 += ex * v2; }
            if (s3 > m3) { float ex = __expf(m3 - s3); z3 = z3 * ex + 1.f; a3 = a3 * ex + v3; m3 = s3; }
            else         { float ex = __expf(s3 - m3); z3 += ex; a3 += ex * v3; }
        }
        o0 += a0 / z0; o1 += a1 / z1; o2 += a2 / z2; o3 += a3 / z3;
    }
    float* ob = attn + (size_t)node * 128;
    ob[lane] = o0; ob[32 + lane] = o1; ob[64 + lane] = o2; ob[96 + lane] = o3;
}

// ---------------- GEMM: C[M x 128] = act(A)[M x 128] @ B[128 x 128] + bias ----------------
template <int MODE>
__global__ __launch_bounds__(128)
void gemm128_kernel(const float* __restrict__ A, const float* __restrict__ B,
                    const float* __restrict__ bias, float* __restrict__ C,
                    int Mrows, const float* __restrict__ resid,
                    const float* __restrict__ skipv) {
    __shared__ __align__(16) float Ast[32][68];
    __shared__ __align__(16) float Bs[32][128];

    int tid = threadIdx.x;
    int r0 = blockIdx.x * 64;
    int tr = tid >> 4;
    int tc = tid & 15;

    u64 acc2[8][4];
#pragma unroll
    for (int i = 0; i < 8; i++)
#pragma unroll
        for (int j = 0; j < 4; j++) acc2[i][j] = 0ull;

    for (int kk = 0; kk < 128; kk += 32) {
        {
            int kq = tid & 7;
            int rr = tid >> 3;
#pragma unroll
            for (int p = 0; p < 4; p++) {
                int row = rr + p * 16;
                int grow = r0 + row;
                float4 va = make_float4(0.f, 0.f, 0.f, 0.f);
                if (grow < Mrows)
                    va = *reinterpret_cast<const float4*>(A + (size_t)grow * 128 + kk + kq * 4);
                if (MODE == 1) {
                    va.x = gelu_f(va.x); va.y = gelu_f(va.y);
                    va.z = gelu_f(va.z); va.w = gelu_f(va.w);
                }
                Ast[kq * 4 + 0][row] = va.x;
                Ast[kq * 4 + 1][row] = va.y;
                Ast[kq * 4 + 2][row] = va.z;
                Ast[kq * 4 + 3][row] = va.w;
            }
        }
        {
            int c4 = tid & 31;
            int kr = tid >> 5;
#pragma unroll
            for (int p = 0; p < 8; p++) {
                int k = kr + p * 4;
                *reinterpret_cast<float4*>(&Bs[k][c4 * 4]) =
                    *reinterpret_cast<const float4*>(B + (size_t)(kk + k) * 128 + c4 * 4);
            }
        }
        __syncthreads();
#pragma unroll 4
        for (int k = 0; k < 32; k++) {
            float4 t0 = *reinterpret_cast<const float4*>(&Ast[k][tr * 8]);
            float4 t1 = *reinterpret_cast<const float4*>(&Ast[k][tr * 8 + 4]);
            u64 a2[8];
            a2[0] = packdup(t0.x); a2[1] = packdup(t0.y);
            a2[2] = packdup(t0.z); a2[3] = packdup(t0.w);
            a2[4] = packdup(t1.x); a2[5] = packdup(t1.y);
            a2[6] = packdup(t1.z); a2[7] = packdup(t1.w);
            ulonglong2 tb0 = *reinterpret_cast<const ulonglong2*>(&Bs[k][tc * 8]);
            ulonglong2 tb1 = *reinterpret_cast<const ulonglong2*>(&Bs[k][tc * 8 + 4]);
            u64 b2[4] = {tb0.x, tb0.y, tb1.x, tb1.y};
#pragma unroll
            for (int i = 0; i < 8; i++)
#pragma unroll
                for (int j = 0; j < 4; j++)
                    fma2(acc2[i][j], a2[i], b2[j]);
        }
        __syncthreads();
    }

    float mix = 1.0f, omix = 0.0f;
    if (MODE == 1) {
        float s = *skipv;
        mix = 1.0f / (1.0f + expf(-s));
        omix = 1.0f - mix;
    }
    float bv[8];
#pragma unroll
    for (int j = 0; j < 8; j++) bv[j] = bias[tc * 8 + j];

#pragma unroll
    for (int i = 0; i < 8; i++) {
        int grow = r0 + tr * 8 + i;
        if (grow >= Mrows) continue;
        float accf[8];
#pragma unroll
        for (int j2 = 0; j2 < 4; j2++)
            unpack2(acc2[i][j2], accf[2 * j2], accf[2 * j2 + 1]);
#pragma unroll
        for (int j = 0; j < 8; j += 4) {
            int col = tc * 8 + j;
            float4 r4;
            r4.x = accf[j + 0] + bv[j + 0];
            r4.y = accf[j + 1] + bv[j + 1];
            r4.z = accf[j + 2] + bv[j + 2];
            r4.w = accf[j + 3] + bv[j + 3];
            if (MODE == 1) {
                float4 old = *reinterpret_cast<const float4*>(resid + (size_t)grow * 128 + col);
                r4.x = mix * r4.x + omix * old.x;
                r4.y = mix * r4.y + omix * old.y;
                r4.z = mix * r4.z + omix * old.z;
                r4.w = mix * r4.w + omix * old.w;
            }
            *reinterpret_cast<float4*>(C + (size_t)grow * 128 + col) = r4;
        }
    }
}

// ---------------- BatchNorm stats + apply ----------------
__global__ void bn_stats_kernel(const float* __restrict__ h, float* __restrict__ stats, int n) {
    __shared__ float s_sum[256], s_sq[256];
    int tid = threadIdx.x;
    int c = tid & 127, half = tid >> 7;
    float sum = 0.f, sq = 0.f;
    for (int r = blockIdx.x * 2 + half; r < n; r += gridDim.x * 2) {
        float v = h[(size_t)r * 128 + c];
        sum += v; sq += v * v;
    }
    s_sum[tid] = sum; s_sq[tid] = sq;
    __syncthreads();
    if (half == 0) {
        atomicAdd(&stats[c], sum + s_sum[tid + 128]);
        atomicAdd(&stats[128 + c], sq + s_sq[tid + 128]);
    }
}

__global__ void bn_apply_kernel(float* __restrict__ h, const float* __restrict__ stats,
                                const float* __restrict__ gamma, const float* __restrict__ beta,
                                int n) {
    int i = blockIdx.x * blockDim.x + threadIdx.x;
    if (i >= n * 128) return;
    int c = i & 127;
    float mean = stats[c] * (1.0f / (float)NN);
    float var = stats[128 + c] * (1.0f / (float)NN) - mean * mean;
    h[i] = (h[i] - mean) * rsqrtf(var + 1e-5f) * gamma[c] + beta[c];
}

// ---------------- relation transforms ----------------
__global__ __launch_bounds__(512)
void rel_transform_kernel(const float* __restrict__ kin, const float* __restrict__ vin,
                          const float* __restrict__ a_rel, const float* __restrict__ m_rel,
                          int n) {
    __shared__ __align__(16) float kvsh[2][256];
    int tid = threadIdx.x;
    int o = tid;
    int r = o >> 7, h = (o >> 5) & 3, e = o & 31;

    u64 w2[32];
    {
        const float* abase = a_rel + (size_t)((r * 4 + h) * 32) * 32 + e;
        const float* mbase = m_rel + (size_t)((r * 4 + h) * 32) * 32 + e;
#pragma unroll
        for (int d = 0; d < 32; d++) w2[d] = pack2(abase[d * 32], mbase[d * 32]);
    }

    for (int n0 = blockIdx.x * 2; n0 < n; n0 += gridDim.x * 2) {
        __syncthreads();
        {
            int which = tid >> 8;
            int cc = tid & 255;
            int node = n0 + which;
            if (node < n) {
                if (cc < 128) kvsh[which][2 * cc] = kin[(size_t)node * 128 + cc];
                else          kvsh[which][2 * (cc - 128) + 1] = vin[(size_t)node * 128 + (cc - 128)];
            }
        }
        __syncthreads();
#pragma unroll
        for (int which = 0; which < 2; which++) {
            int node = n0 + which;
            if (node >= n) break;
            u64 acc = 0ull;
            const ulonglong2* kv = reinterpret_cast<const ulonglong2*>(&kvsh[which][h * 64]);
#pragma unroll
            for (int d2 = 0; d2 < 16; d2++) {
                ulonglong2 p = kv[d2];
                fma2(acc, p.x, w2[2 * d2]);
                fma2(acc, p.y, w2[2 * d2 + 1]);
            }
            float accK, accV;
            unpack2(acc, accK, accV);
            g_kall[(size_t)node * 512 + o] = accK;
            g_vall[(size_t)node * 512 + o] = accV;
        }
    }
}

// ---------------- gather ----------------
__global__ void gather_kernel(const int* __restrict__ idx, const float* __restrict__ h,
                              float* __restrict__ out) {
    int gid = blockIdx.x * blockDim.x + threadIdx.x;
    if (gid >= MMOUT * 32) return;
    int m = gid >> 5, c4 = gid & 31;
    reinterpret_cast<float4*>(out)[(size_t)m * 32 + c4] =
        reinterpret_cast<const float4*>(h + (size_t)idx[m] * 128)[c4];
}

// ---------------- launch ----------------
extern "C" void kernel_launch(void* const* d_in, const int* in_sizes, int n_in,
                              void* d_out, int out_size) {
    const float* x        = (const float*)d_in[0];
    const float* proj_w   = (const float*)d_in[1];
    const float* proj_b   = (const float*)d_in[2];
    const float* bn_gamma = (const float*)d_in[3];
    const float* bn_beta  = (const float*)d_in[4];
    const float* q_w      = (const float*)d_in[5];
    const float* q_b      = (const float*)d_in[6];
    const float* k_w      = (const float*)d_in[7];
    const float* k_b      = (const float*)d_in[8];
    const float* v_w      = (const float*)d_in[9];
    const float* v_b      = (const float*)d_in[10];
    const float* a_w      = (const float*)d_in[11];
    const float* a_b      = (const float*)d_in[12];
    const float* skip     = (const float*)d_in[13];
    const float* a_rel    = (const float*)d_in[14];
    const float* m_rel    = (const float*)d_in[15];
    const float* p_rel    = (const float*)d_in[16];
    const int*   edge_idx = (const int*)d_in[17];
    const int*   edge_typ = (const int*)d_in[18];
    const int*   idx      = (const int*)d_in[19];
    float*       out      = (float*)d_out;

    float *p_h, *p_q, *p_k, *p_v, *p_attn, *p_stats;
    int *p_counts, *p_offs, *p_cursor, *p_bsum, *p_boff, *p_ssrc;
    cudaGetSymbolAddress((void**)&p_h, g_h);
    cudaGetSymbolAddress((void**)&p_q, g_q);
    cudaGetSymbolAddress((void**)&p_k, g_k);
    cudaGetSymbolAddress((void**)&p_v, g_v);
    cudaGetSymbolAddress((void**)&p_attn, g_attn);
    cudaGetSymbolAddress((void**)&p_stats, g_stats);
    cudaGetSymbolAddress((void**)&p_counts, g_counts);
    cudaGetSymbolAddress((void**)&p_offs, g_offs);
    cudaGetSymbolAddress((void**)&p_cursor, g_cursor);
    cudaGetSymbolAddress((void**)&p_bsum, g_bsum);
    cudaGetSymbolAddress((void**)&p_boff, g_boff);
    cudaGetSymbolAddress((void**)&p_ssrc, g_ssrc);

    const int gemmGrid = (NN + 63) / 64;
    const int eBlocks = (EE + 255) / 256;

    // ---- CSR build (once; topology is layer-invariant) ----
    fill_zero_kernel<<<(NSEG + 255) / 256, 256>>>((unsigned*)p_counts, NSEG);
    hist_kernel<<<eBlocks, 256>>>(edge_idx, edge_typ, p_counts);
    scan_pass1<<<SCAN_B, 1024>>>(p_counts, p_bsum);
    scan_pass2<<<1, 32>>>(p_bsum, p_boff, p_offs);
    scan_pass3<<<SCAN_B, 1024>>>(p_counts, p_boff, p_offs, p_cursor);
    scatter_kernel<<<eBlocks, 256>>>(edge_idx, edge_typ, p_cursor, p_ssrc);

    // ---- proj + BN ----
    fill_zero_kernel<<<1, 256>>>((unsigned*)p_stats, 2 * HIDN);
    gemm128_kernel<0><<<gemmGrid, 128>>>(x, proj_w, proj_b, p_h, NN, nullptr, nullptr);
    bn_stats_kernel<<<512, 256>>>(p_h, p_stats, NN);
    bn_apply_kernel<<<(NN * 128 + 255) / 256, 256>>>(p_h, p_stats, bn_gamma, bn_beta, NN);

    for (int l = 0; l < LLAY; l++) {
        const float* qwl = q_w + (size_t)l * 128 * 128;
        const float* kwl = k_w + (size_t)l * 128 * 128;
        const float* vwl = v_w + (size_t)l * 128 * 128;
        const float* awl = a_w + (size_t)l * 128 * 128;
        const float* qbl = q_b + (size_t)l * 128;
        const float* kbl = k_b + (size_t)l * 128;
        const float* vbl = v_b + (size_t)l * 128;
        const float* abl = a_b + (size_t)l * 128;
        const float* arl = a_rel + (size_t)l * RR * HH * DDIM * DDIM;
        const float* mrl = m_rel + (size_t)l * RR * HH * DDIM * DDIM;
        const float* prl = p_rel + (size_t)l * RR * HH;
        const float* skl = skip + l;

        gemm128_kernel<0><<<gemmGrid, 128>>>(p_h, qwl, qbl, p_q, NN, nullptr, nullptr);
        gemm128_kernel<0><<<gemmGrid, 128>>>(p_h, kwl, kbl, p_k, NN, nullptr, nullptr);
        gemm128_kernel<0><<<gemmGrid, 128>>>(p_h, vwl, vbl, p_v, NN, nullptr, nullptr);

        rel_transform_kernel<<<4096, 512>>>(p_k, p_v, arl, mrl, NN);

        edge_attn_kernel<<<(NN * 32 + 255) / 256, 256>>>(p_q, p_offs, p_ssrc, prl, p_attn);

        gemm128_kernel<1><<<gemmGrid, 128>>>(p_attn, awl, abl, p_h, NN, p_h, skl);
    }

    gather_kernel<<<(MMOUT * 32 + 255) / 256, 256>>>(idx, p_h, out);
}

// round 4
// speedup vs baseline: 1.3725x; 1.0537x over previous
#include <cuda_runtime.h>
#include <math.h>

#define NN   50000
#define EE   600000
#define HIDN 128
#define HH   4
#define DDIM 32
#define RR   4
#define LLAY 2
#define MMOUT 10000
#define NSEG (NN * RR)                 // 200000 softmax segments
#define SCAN_CHUNK 4096
#define SCAN_B ((NSEG + SCAN_CHUNK - 1) / SCAN_CHUNK)   // 49

typedef unsigned long long u64;

// ---------------- scratch (device globals; no allocations allowed) ----------------
__device__ float g_h[NN * HIDN];
__device__ float g_q[NN * HIDN];
__device__ float g_k[NN * HIDN];
__device__ float g_v[NN * HIDN];
__device__ float g_kall[NN * RR * HIDN];   // [n][r][h][e]
__device__ float g_vall[NN * RR * HIDN];
__device__ float g_attn[NN * HIDN];
__device__ float g_stats[2 * HIDN];
// CSR scratch
__device__ int   g_counts[NSEG];
__device__ int   g_offs[NSEG + 1];
__device__ int   g_cursor[NSEG];
__device__ int   g_bsum[SCAN_B];
__device__ int   g_boff[SCAN_B];
__device__ int   g_ssrc[EE];

// ---------------- f32x2 helpers ----------------
__device__ __forceinline__ void fma2(u64& d, u64 a, u64 b) {
    asm("fma.rn.f32x2 %0, %1, %2, %0;" : "+l"(d) : "l"(a), "l"(b));
}
__device__ __forceinline__ u64 packdup(float s) {
    u64 r; asm("mov.b64 %0, {%1, %1};" : "=l"(r) : "f"(s)); return r;
}
__device__ __forceinline__ u64 pack2(float lo, float hi) {
    u64 r; asm("mov.b64 %0, {%1, %2};" : "=l"(r) : "f"(lo), "f"(hi)); return r;
}
__device__ __forceinline__ void unpack2(u64 v, float& lo, float& hi) {
    asm("mov.b64 {%0, %1}, %2;" : "=f"(lo), "=f"(hi) : "l"(v));
}

__device__ __forceinline__ float gelu_f(float x) {
    return 0.5f * x * (1.0f + erff(x * 0.7071067811865475f));
}

// ---------------- fill ----------------
__global__ void fill_zero_kernel(unsigned* __restrict__ p, int n) {
    int i = blockIdx.x * blockDim.x + threadIdx.x;
    if (i < n) p[i] = 0u;
}

// ================= CSR build: counting sort of edges by seg = dst*4 + rel =================
__global__ void hist_kernel(const int* __restrict__ ei, const int* __restrict__ et,
                            int* __restrict__ counts) {
    int e = blockIdx.x * blockDim.x + threadIdx.x;
    if (e >= EE) return;
    int dst = ei[EE + e], r = et[e];
    atomicAdd(&counts[dst * 4 + r], 1);
}

__global__ __launch_bounds__(1024)
void scan_pass1(const int* __restrict__ counts, int* __restrict__ bsum) {
    __shared__ int swarp[32];
    int b = blockIdx.x, t = threadIdx.x;
    int base = b * SCAN_CHUNK + t * 4;
    int tot = 0;
#pragma unroll
    for (int j = 0; j < 4; j++) {
        int idx = base + j;
        tot += (idx < NSEG) ? counts[idx] : 0;
    }
#pragma unroll
    for (int d = 16; d; d >>= 1) tot += __shfl_xor_sync(0xffffffffu, tot, d);
    if ((t & 31) == 0) swarp[t >> 5] = tot;
    __syncthreads();
    if (t < 32) {
        int v = swarp[t];
#pragma unroll
        for (int d = 16; d; d >>= 1) v += __shfl_xor_sync(0xffffffffu, v, d);
        if (t == 0) bsum[b] = v;
    }
}

__global__ void scan_pass2(const int* __restrict__ bsum, int* __restrict__ boff,
                           int* __restrict__ offs) {
    if (threadIdx.x == 0 && blockIdx.x == 0) {
        int run = 0;
        for (int i = 0; i < SCAN_B; i++) { boff[i] = run; run += bsum[i]; }
        offs[NSEG] = run;
    }
}

__global__ __launch_bounds__(1024)
void scan_pass3(const int* __restrict__ counts, const int* __restrict__ boff,
                int* __restrict__ offs, int* __restrict__ cursor) {
    __shared__ int swarp[32];
    int b = blockIdx.x, t = threadIdx.x;
    int base = b * SCAN_CHUNK + t * 4;
    int c[4]; int tot = 0;
#pragma unroll
    for (int j = 0; j < 4; j++) {
        int idx = base + j;
        c[j] = (idx < NSEG) ? counts[idx] : 0;
        tot += c[j];
    }
    int lane = t & 31, w = t >> 5;
    int v = tot;
#pragma unroll
    for (int d = 1; d < 32; d <<= 1) {
        int n = __shfl_up_sync(0xffffffffu, v, d);
        if (lane >= d) v += n;
    }
    if (lane == 31) swarp[w] = v;
    __syncthreads();
    if (w == 0) {
        int sv = swarp[lane];
#pragma unroll
        for (int d = 1; d < 32; d <<= 1) {
            int n = __shfl_up_sync(0xffffffffu, sv, d);
            if (lane >= d) sv += n;
        }
        swarp[lane] = sv;
    }
    __syncthreads();
    int excl = v - tot + ((w > 0) ? swarp[w - 1] : 0) + boff[b];
#pragma unroll
    for (int j = 0; j < 4; j++) {
        int idx = base + j;
        if (idx < NSEG) { offs[idx] = excl; cursor[idx] = excl; }
        excl += c[j];
    }
}

__global__ void scatter_kernel(const int* __restrict__ ei, const int* __restrict__ et,
                               int* __restrict__ cursor, int* __restrict__ ssrc) {
    int e = blockIdx.x * blockDim.x + threadIdx.x;
    if (e >= EE) return;
    int src = ei[e], dst = ei[EE + e], r = et[e];
    int pos = atomicAdd(&cursor[dst * 4 + r], 1);
    ssrc[pos] = src;
}

// ================= fused edge attention v2: one warp per dst node =================
// Lane l owns dims 4l..4l+3 of the 128-float (h,e) row; head h = l>>3.
// Dot per head reduces over its 8-lane group (3 shuffles). Branchless online softmax.
__global__ __launch_bounds__(256)
void edge_attn_kernel(const float* __restrict__ q, const int* __restrict__ offs,
                      const int* __restrict__ ssrc, const float* __restrict__ p_rel,
                      float* __restrict__ attn) {
    int wid = (blockIdx.x * (int)blockDim.x + (int)threadIdx.x) >> 5;
    int lane = threadIdx.x & 31;
    if (wid >= NN) return;
    const int node = wid;
    const int h = lane >> 3;
    const float SCALE = 0.17677669529663687f;   // 1/sqrt(32)

    float4 q4 = *reinterpret_cast<const float4*>(q + (size_t)node * 128 + lane * 4);
    float4 o4 = make_float4(0.f, 0.f, 0.f, 0.f);

    int obase = node * 4;
#pragma unroll
    for (int r = 0; r < 4; r++) {
        int s = offs[obase + r], e = offs[obase + r + 1];
        if (s >= e) continue;
        float pr = p_rel[r * 4 + h] * SCALE;
        float m = -INFINITY, z = 0.f;
        float4 a4 = make_float4(0.f, 0.f, 0.f, 0.f);

        for (int pos = s; pos < e; pos++) {
            int src = __ldg(&ssrc[pos]);
            const float* kb = g_kall + (size_t)src * 512 + r * 128 + lane * 4;
            const float* vb = g_vall + (size_t)src * 512 + r * 128 + lane * 4;
            float4 k4 = *reinterpret_cast<const float4*>(kb);
            float4 v4 = *reinterpret_cast<const float4*>(vb);
            float sc = q4.x * k4.x + q4.y * k4.y + q4.z * k4.z + q4.w * k4.w;
            sc += __shfl_xor_sync(0xffffffffu, sc, 1);
            sc += __shfl_xor_sync(0xffffffffu, sc, 2);
            sc += __shfl_xor_sync(0xffffffffu, sc, 4);
            sc *= pr;
            float nm = fmaxf(m, sc);
            float eo = __expf(m - nm);
            float es = __expf(sc - nm);
            z = z * eo + es;
            a4.x = a4.x * eo + es * v4.x;
            a4.y = a4.y * eo + es * v4.y;
            a4.z = a4.z * eo + es * v4.z;
            a4.w = a4.w * eo + es * v4.w;
            m = nm;
        }
        float iz = 1.0f / z;
        o4.x += a4.x * iz; o4.y += a4.y * iz;
        o4.z += a4.z * iz; o4.w += a4.w * iz;
    }
    *reinterpret_cast<float4*>(attn + (size_t)node * 128 + lane * 4) = o4;
}

// ---------------- GEMM: C[M x 128] = act(A)[M x 128] @ B[128 x 128] + bias ----------------
template <int MODE>
__global__ __launch_bounds__(128)
void gemm128_kernel(const float* __restrict__ A, const float* __restrict__ B,
                    const float* __restrict__ bias, float* __restrict__ C,
                    int Mrows, const float* __restrict__ resid,
                    const float* __restrict__ skipv) {
    __shared__ __align__(16) float Ast[32][68];
    __shared__ __align__(16) float Bs[32][128];

    int tid = threadIdx.x;
    int r0 = blockIdx.x * 64;
    int tr = tid >> 4;
    int tc = tid & 15;

    u64 acc2[8][4];
#pragma unroll
    for (int i = 0; i < 8; i++)
#pragma unroll
        for (int j = 0; j < 4; j++) acc2[i][j] = 0ull;

    for (int kk = 0; kk < 128; kk += 32) {
        {
            int kq = tid & 7;
            int rr = tid >> 3;
#pragma unroll
            for (int p = 0; p < 4; p++) {
                int row = rr + p * 16;
                int grow = r0 + row;
                float4 va = make_float4(0.f, 0.f, 0.f, 0.f);
                if (grow < Mrows)
                    va = *reinterpret_cast<const float4*>(A + (size_t)grow * 128 + kk + kq * 4);
                if (MODE == 1) {
                    va.x = gelu_f(va.x); va.y = gelu_f(va.y);
                    va.z = gelu_f(va.z); va.w = gelu_f(va.w);
                }
                Ast[kq * 4 + 0][row] = va.x;
                Ast[kq * 4 + 1][row] = va.y;
                Ast[kq * 4 + 2][row] = va.z;
                Ast[kq * 4 + 3][row] = va.w;
            }
        }
        {
            int c4 = tid & 31;
            int kr = tid >> 5;
#pragma unroll
            for (int p = 0; p < 8; p++) {
                int k = kr + p * 4;
                *reinterpret_cast<float4*>(&Bs[k][c4 * 4]) =
                    *reinterpret_cast<const float4*>(B + (size_t)(kk + k) * 128 + c4 * 4);
            }
        }
        __syncthreads();
#pragma unroll 4
        for (int k = 0; k < 32; k++) {
            float4 t0 = *reinterpret_cast<const float4*>(&Ast[k][tr * 8]);
            float4 t1 = *reinterpret_cast<const float4*>(&Ast[k][tr * 8 + 4]);
            u64 a2[8];
            a2[0] = packdup(t0.x); a2[1] = packdup(t0.y);
            a2[2] = packdup(t0.z); a2[3] = packdup(t0.w);
            a2[4] = packdup(t1.x); a2[5] = packdup(t1.y);
            a2[6] = packdup(t1.z); a2[7] = packdup(t1.w);
            ulonglong2 tb0 = *reinterpret_cast<const ulonglong2*>(&Bs[k][tc * 8]);
            ulonglong2 tb1 = *reinterpret_cast<const ulonglong2*>(&Bs[k][tc * 8 + 4]);
            u64 b2[4] = {tb0.x, tb0.y, tb1.x, tb1.y};
#pragma unroll
            for (int i = 0; i < 8; i++)
#pragma unroll
                for (int j = 0; j < 4; j++)
                    fma2(acc2[i][j], a2[i], b2[j]);
        }
        __syncthreads();
    }

    float mix = 1.0f, omix = 0.0f;
    if (MODE == 1) {
        float s = *skipv;
        mix = 1.0f / (1.0f + expf(-s));
        omix = 1.0f - mix;
    }
    float bv[8];
#pragma unroll
    for (int j = 0; j < 8; j++) bv[j] = bias[tc * 8 + j];

#pragma unroll
    for (int i = 0; i < 8; i++) {
        int grow = r0 + tr * 8 + i;
        if (grow >= Mrows) continue;
        float accf[8];
#pragma unroll
        for (int j2 = 0; j2 < 4; j2++)
            unpack2(acc2[i][j2], accf[2 * j2], accf[2 * j2 + 1]);
#pragma unroll
        for (int j = 0; j < 8; j += 4) {
            int col = tc * 8 + j;
            float4 r4;
            r4.x = accf[j + 0] + bv[j + 0];
            r4.y = accf[j + 1] + bv[j + 1];
            r4.z = accf[j + 2] + bv[j + 2];
            r4.w = accf[j + 3] + bv[j + 3];
            if (MODE == 1) {
                float4 old = *reinterpret_cast<const float4*>(resid + (size_t)grow * 128 + col);
                r4.x = mix * r4.x + omix * old.x;
                r4.y = mix * r4.y + omix * old.y;
                r4.z = mix * r4.z + omix * old.z;
                r4.w = mix * r4.w + omix * old.w;
            }
            *reinterpret_cast<float4*>(C + (size_t)grow * 128 + col) = r4;
        }
    }
}

// ---------------- BatchNorm stats + apply ----------------
__global__ void bn_stats_kernel(const float* __restrict__ h, float* __restrict__ stats, int n) {
    __shared__ float s_sum[256], s_sq[256];
    int tid = threadIdx.x;
    int c = tid & 127, half = tid >> 7;
    float sum = 0.f, sq = 0.f;
    for (int r = blockIdx.x * 2 + half; r < n; r += gridDim.x * 2) {
        float v = h[(size_t)r * 128 + c];
        sum += v; sq += v * v;
    }
    s_sum[tid] = sum; s_sq[tid] = sq;
    __syncthreads();
    if (half == 0) {
        atomicAdd(&stats[c], sum + s_sum[tid + 128]);
        atomicAdd(&stats[128 + c], sq + s_sq[tid + 128]);
    }
}

__global__ void bn_apply_kernel(float* __restrict__ h, const float* __restrict__ stats,
                                const float* __restrict__ gamma, const float* __restrict__ beta,
                                int n) {
    int i = blockIdx.x * blockDim.x + threadIdx.x;
    if (i >= n * 128) return;
    int c = i & 127;
    float mean = stats[c] * (1.0f / (float)NN);
    float var = stats[128 + c] * (1.0f / (float)NN) - mean * mean;
    h[i] = (h[i] - mean) * rsqrtf(var + 1e-5f) * gamma[c] + beta[c];
}

// ---------------- relation transforms ----------------
__global__ __launch_bounds__(512)
void rel_transform_kernel(const float* __restrict__ kin, const float* __restrict__ vin,
                          const float* __restrict__ a_rel, const float* __restrict__ m_rel,
                          int n) {
    __shared__ __align__(16) float kvsh[2][256];
    int tid = threadIdx.x;
    int o = tid;
    int r = o >> 7, h = (o >> 5) & 3, e = o & 31;

    u64 w2[32];
    {
        const float* abase = a_rel + (size_t)((r * 4 + h) * 32) * 32 + e;
        const float* mbase = m_rel + (size_t)((r * 4 + h) * 32) * 32 + e;
#pragma unroll
        for (int d = 0; d < 32; d++) w2[d] = pack2(abase[d * 32], mbase[d * 32]);
    }

    for (int n0 = blockIdx.x * 2; n0 < n; n0 += gridDim.x * 2) {
        __syncthreads();
        {
            int which = tid >> 8;
            int cc = tid & 255;
            int node = n0 + which;
            if (node < n) {
                if (cc < 128) kvsh[which][2 * cc] = kin[(size_t)node * 128 + cc];
                else          kvsh[which][2 * (cc - 128) + 1] = vin[(size_t)node * 128 + (cc - 128)];
            }
        }
        __syncthreads();
#pragma unroll
        for (int which = 0; which < 2; which++) {
            int node = n0 + which;
            if (node >= n) break;
            u64 acc = 0ull;
            const ulonglong2* kv = reinterpret_cast<const ulonglong2*>(&kvsh[which][h * 64]);
#pragma unroll
            for (int d2 = 0; d2 < 16; d2++) {
                ulonglong2 p = kv[d2];
                fma2(acc, p.x, w2[2 * d2]);
                fma2(acc, p.y, w2[2 * d2 + 1]);
            }
            float accK, accV;
            unpack2(acc, accK, accV);
            g_kall[(size_t)node * 512 + o] = accK;
            g_vall[(size_t)node * 512 + o] = accV;
        }
    }
}

// ---------------- gather ----------------
__global__ void gather_kernel(const int* __restrict__ idx, const float* __restrict__ h,
                              float* __restrict__ out) {
    int gid = blockIdx.x * blockDim.x + threadIdx.x;
    if (gid >= MMOUT * 32) return;
    int m = gid >> 5, c4 = gid & 31;
    reinterpret_cast<float4*>(out)[(size_t)m * 32 + c4] =
        reinterpret_cast<const float4*>(h + (size_t)idx[m] * 128)[c4];
}

// ---------------- launch ----------------
extern "C" void kernel_launch(void* const* d_in, const int* in_sizes, int n_in,
                              void* d_out, int out_size) {
    const float* x        = (const float*)d_in[0];
    const float* proj_w   = (const float*)d_in[1];
    const float* proj_b   = (const float*)d_in[2];
    const float* bn_gamma = (const float*)d_in[3];
    const float* bn_beta  = (const float*)d_in[4];
    const float* q_w      = (const float*)d_in[5];
    const float* q_b      = (const float*)d_in[6];
    const float* k_w      = (const float*)d_in[7];
    const float* k_b      = (const float*)d_in[8];
    const float* v_w      = (const float*)d_in[9];
    const float* v_b      = (const float*)d_in[10];
    const float* a_w      = (const float*)d_in[11];
    const float* a_b      = (const float*)d_in[12];
    const float* skip     = (const float*)d_in[13];
    const float* a_rel    = (const float*)d_in[14];
    const float* m_rel    = (const float*)d_in[15];
    const float* p_rel    = (const float*)d_in[16];
    const int*   edge_idx = (const int*)d_in[17];
    const int*   edge_typ = (const int*)d_in[18];
    const int*   idx      = (const int*)d_in[19];
    float*       out      = (float*)d_out;

    float *p_h, *p_q, *p_k, *p_v, *p_attn, *p_stats;
    int *p_counts, *p_offs, *p_cursor, *p_bsum, *p_boff, *p_ssrc;
    cudaGetSymbolAddress((void**)&p_h, g_h);
    cudaGetSymbolAddress((void**)&p_q, g_q);
    cudaGetSymbolAddress((void**)&p_k, g_k);
    cudaGetSymbolAddress((void**)&p_v, g_v);
    cudaGetSymbolAddress((void**)&p_attn, g_attn);
    cudaGetSymbolAddress((void**)&p_stats, g_stats);
    cudaGetSymbolAddress((void**)&p_counts, g_counts);
    cudaGetSymbolAddress((void**)&p_offs, g_offs);
    cudaGetSymbolAddress((void**)&p_cursor, g_cursor);
    cudaGetSymbolAddress((void**)&p_bsum, g_bsum);
    cudaGetSymbolAddress((void**)&p_boff, g_boff);
    cudaGetSymbolAddress((void**)&p_ssrc, g_ssrc);

    const int gemmGrid = (NN + 63) / 64;
    const int eBlocks = (EE + 255) / 256;

    // ---- proj + BN first (puts GEMMs at profiled launch slots) ----
    fill_zero_kernel<<<1, 256>>>((unsigned*)p_stats, 2 * HIDN);
    gemm128_kernel<0><<<gemmGrid, 128>>>(x, proj_w, proj_b, p_h, NN, nullptr, nullptr);
    bn_stats_kernel<<<512, 256>>>(p_h, p_stats, NN);
    bn_apply_kernel<<<(NN * 128 + 255) / 256, 256>>>(p_h, p_stats, bn_gamma, bn_beta, NN);

    // layer 0 QKV (launches 5,6,7 — ncu -s 5 lands here)
    gemm128_kernel<0><<<gemmGrid, 128>>>(p_h, q_w, q_b, p_q, NN, nullptr, nullptr);
    gemm128_kernel<0><<<gemmGrid, 128>>>(p_h, k_w, k_b, p_k, NN, nullptr, nullptr);
    gemm128_kernel<0><<<gemmGrid, 128>>>(p_h, v_w, v_b, p_v, NN, nullptr, nullptr);

    // ---- CSR build (topology layer-invariant; must finish before edge_attn) ----
    fill_zero_kernel<<<(NSEG + 255) / 256, 256>>>((unsigned*)p_counts, NSEG);
    hist_kernel<<<eBlocks, 256>>>(edge_idx, edge_typ, p_counts);
    scan_pass1<<<SCAN_B, 1024>>>(p_counts, p_bsum);
    scan_pass2<<<1, 32>>>(p_bsum, p_boff, p_offs);
    scan_pass3<<<SCAN_B, 1024>>>(p_counts, p_boff, p_offs, p_cursor);
    scatter_kernel<<<eBlocks, 256>>>(edge_idx, edge_typ, p_cursor, p_ssrc);

    for (int l = 0; l < LLAY; l++) {
        const float* qwl = q_w + (size_t)l * 128 * 128;
        const float* kwl = k_w + (size_t)l * 128 * 128;
        const float* vwl = v_w + (size_t)l * 128 * 128;
        const float* awl = a_w + (size_t)l * 128 * 128;
        const float* abl = a_b + (size_t)l * 128;
        const float* arl = a_rel + (size_t)l * RR * HH * DDIM * DDIM;
        const float* mrl = m_rel + (size_t)l * RR * HH * DDIM * DDIM;
        const float* prl = p_rel + (size_t)l * RR * HH;
        const float* skl = skip + l;

        if (l > 0) {
            gemm128_kernel<0><<<gemmGrid, 128>>>(p_h, qwl, q_b + (size_t)l * 128, p_q, NN, nullptr, nullptr);
            gemm128_kernel<0><<<gemmGrid, 128>>>(p_h, kwl, k_b + (size_t)l * 128, p_k, NN, nullptr, nullptr);
            gemm128_kernel<0><<<gemmGrid, 128>>>(p_h, vwl, v_b + (size_t)l * 128, p_v, NN, nullptr, nullptr);
        }

        rel_transform_kernel<<<4096, 512>>>(p_k, p_v, arl, mrl, NN);

        edge_attn_kernel<<<(NN * 32 + 255) / 256, 256>>>(p_q, p_offs, p_ssrc, prl, p_attn);

        gemm128_kernel<1><<<gemmGrid, 128>>>(p_attn, awl, abl, p_h, NN, p_h, skl);
    }

    gather_kernel<<<(MMOUT * 32 + 255) / 256, 256>>>(idx, p_h, out);
}